// round 1
// baseline (speedup 1.0000x reference)
#include <cuda_runtime.h>
#include <cuda_bf16.h>
#include <cstdint>

// Problem shape (fixed by the dataset)
#define T_TOK 8192
#define K_IN  4096
#define N_OUT 4096
#define GROUP 32

// Dequantized scratch (bf16 is exact for MXFP4 values)
__device__ __nv_bfloat16 g_xq[(size_t)T_TOK * K_IN];   // 64 MB
__device__ __nv_bfloat16 g_wq[(size_t)N_OUT * K_IN];   // 32 MB

// ---------------------------------------------------------------------------
// Kernel 1: fused Hadamard rotate + MXFP4 quant-dequant for x and weight.
// One warp handles one group of 32 contiguous elements per iteration.
// FWHT over lanes == t @ H_sylvester (H symmetric), then * 1/sqrt(32).
// ---------------------------------------------------------------------------
__global__ void rotate_quant_kernel(const float* __restrict__ x,
                                    const float* __restrict__ w,
                                    __nv_bfloat16* __restrict__ xq,
                                    __nv_bfloat16* __restrict__ wq) {
    const long long XG  = (long long)T_TOK * K_IN / GROUP;   // x groups
    const long long TOT = XG + (long long)N_OUT * K_IN / GROUP;

    const int lane = threadIdx.x & 31;
    long long warp  = (long long)blockIdx.x * (blockDim.x >> 5) + (threadIdx.x >> 5);
    long long nwarp = (long long)gridDim.x * (blockDim.x >> 5);

    for (long long gidx = warp; gidx < TOT; gidx += nwarp) {
        const float* src;
        __nv_bfloat16* dst;
        long long base;
        if (gidx < XG) { src = x; dst = xq; base = gidx * GROUP; }
        else           { src = w; dst = wq; base = (gidx - XG) * GROUP; }

        float v = src[base + lane];

        // 5-stage FWHT across the warp: v_j = sum_k (-1)^popc(j&k) t_k
        #pragma unroll
        for (int m = 1; m < 32; m <<= 1) {
            float o = __shfl_xor_sync(0xffffffffu, v, m);
            v = (lane & m) ? (o - v) : (v + o);
        }
        v *= 0.17677669529663688f;   // 1/sqrt(32), matches H entries

        // group amax
        float amax = fabsf(v);
        #pragma unroll
        for (int m = 16; m >= 1; m >>= 1)
            amax = fmaxf(amax, __shfl_xor_sync(0xffffffffu, amax, m));
        amax = fmaxf(amax, 1.1754943508222875e-38f);  // 2^-126

        // E8M0 shared scale: 2^(floor(log2(amax)) - 2), clipped
        int e = (int)((__float_as_uint(amax) >> 23) & 0xFF) - 127 - 2;
        e = max(-127, min(127, e));
        float scale = ldexpf(1.0f, e);

        float s  = v / scale;                 // exact (power of 2)
        float a  = fminf(fabsf(s), 6.0f);
        // nearest E2M1 magnitude; strictly-greater midpoints per reference
        float q;
        if (a > 2.5f)        q = (a > 5.0f)  ? 6.0f : ((a > 3.5f)  ? 4.0f : 3.0f);
        else if (a > 1.25f)  q = (a > 1.75f) ? 2.0f : 1.5f;
        else                 q = (a > 0.75f) ? 1.0f : ((a > 0.25f) ? 0.5f : 0.0f);

        float r = copysignf(q, s) * scale;    // exactly representable in bf16
        dst[base + lane] = __float2bfloat16(r);
    }
}

// ---------------------------------------------------------------------------
// Kernel 2: bf16 GEMM  C[M,N] = A[M,K] @ B[N,K]^T + bias,  fp32 accumulate.
// 128x128x32 tiles, 256 threads, 8 warps (4x2), mma.sync.m16n8k16,
// double-buffered cp.async, 16B-padded smem rows (bank-conflict-free).
// ---------------------------------------------------------------------------
#define BM 128
#define BN 128
#define BK 32
#define SSTRIDE (BK + 8)   // bf16 elements per smem row (16B pad)

__global__ __launch_bounds__(256, 1)
void gemm_bf16_kernel(const __nv_bfloat16* __restrict__ A,
                      const __nv_bfloat16* __restrict__ B,
                      const float* __restrict__ bias,
                      float* __restrict__ C,
                      int M, int N, int K) {
    __shared__ __nv_bfloat16 sA[2][BM * SSTRIDE];
    __shared__ __nv_bfloat16 sB[2][BN * SSTRIDE];

    const int tid  = threadIdx.x;
    const int bm   = blockIdx.y;
    const int bn   = blockIdx.x;

    const __nv_bfloat16* Ablk = A + (long long)bm * BM * K;
    const __nv_bfloat16* Bblk = B + (long long)bn * BN * K;

    const int warp = tid >> 5, lane = tid & 31;
    const int wm = warp & 3;        // 0..3 (rows)
    const int wn = warp >> 2;       // 0..1 (cols)
    const int g  = lane >> 2;       // 0..7
    const int tg = lane & 3;        // 0..3

    float acc[2][8][4];
    #pragma unroll
    for (int mi = 0; mi < 2; mi++)
        #pragma unroll
        for (int ni = 0; ni < 8; ni++)
            #pragma unroll
            for (int r = 0; r < 4; r++) acc[mi][ni][r] = 0.0f;

    auto load_tile = [&](int buf, int kt) {
        const int k0 = kt * BK;
        #pragma unroll
        for (int i = 0; i < 2; i++) {
            int ch  = tid + i * 256;          // 0..511
            int row = ch >> 2;                // 0..127
            int cc  = (ch & 3) * 8;           // 0,8,16,24
            unsigned dA = (unsigned)__cvta_generic_to_shared(&sA[buf][row * SSTRIDE + cc]);
            asm volatile("cp.async.cg.shared.global [%0], [%1], 16;\n"
                         :: "r"(dA), "l"(Ablk + (long long)row * K + k0 + cc));
            unsigned dB = (unsigned)__cvta_generic_to_shared(&sB[buf][row * SSTRIDE + cc]);
            asm volatile("cp.async.cg.shared.global [%0], [%1], 16;\n"
                         :: "r"(dB), "l"(Bblk + (long long)row * K + k0 + cc));
        }
        asm volatile("cp.async.commit_group;\n");
    };

    load_tile(0, 0);
    asm volatile("cp.async.wait_group 0;\n");
    __syncthreads();

    const int KT = K / BK;
    for (int kt = 0; kt < KT; ++kt) {
        const int buf = kt & 1;
        if (kt + 1 < KT) load_tile(buf ^ 1, kt + 1);

        #pragma unroll
        for (int kk = 0; kk < BK; kk += 16) {
            uint32_t afr[2][4];
            #pragma unroll
            for (int mi = 0; mi < 2; mi++) {
                const int r0 = wm * 32 + mi * 16 + g;
                const __nv_bfloat16* pa = sA[buf];
                afr[mi][0] = *(const uint32_t*)&pa[(r0    ) * SSTRIDE + kk + tg * 2    ];
                afr[mi][1] = *(const uint32_t*)&pa[(r0 + 8) * SSTRIDE + kk + tg * 2    ];
                afr[mi][2] = *(const uint32_t*)&pa[(r0    ) * SSTRIDE + kk + tg * 2 + 8];
                afr[mi][3] = *(const uint32_t*)&pa[(r0 + 8) * SSTRIDE + kk + tg * 2 + 8];
            }
            #pragma unroll
            for (int ni = 0; ni < 8; ni++) {
                const int c0 = wn * 64 + ni * 8 + g;
                const __nv_bfloat16* pb = sB[buf];
                uint32_t b0 = *(const uint32_t*)&pb[c0 * SSTRIDE + kk + tg * 2    ];
                uint32_t b1 = *(const uint32_t*)&pb[c0 * SSTRIDE + kk + tg * 2 + 8];
                #pragma unroll
                for (int mi = 0; mi < 2; mi++) {
                    float* c = acc[mi][ni];
                    asm volatile(
                        "mma.sync.aligned.m16n8k16.row.col.f32.bf16.bf16.f32 "
                        "{%0,%1,%2,%3},{%4,%5,%6,%7},{%8,%9},{%0,%1,%2,%3};\n"
                        : "+f"(c[0]), "+f"(c[1]), "+f"(c[2]), "+f"(c[3])
                        : "r"(afr[mi][0]), "r"(afr[mi][1]),
                          "r"(afr[mi][2]), "r"(afr[mi][3]),
                          "r"(b0), "r"(b1));
                }
            }
        }
        asm volatile("cp.async.wait_group 0;\n");
        __syncthreads();
    }

    // Epilogue: add bias, fp32 store
    const long long rowbase = (long long)bm * BM + wm * 32;
    const int colbase = bn * BN + wn * 64;
    #pragma unroll
    for (int mi = 0; mi < 2; mi++) {
        #pragma unroll
        for (int ni = 0; ni < 8; ni++) {
            const int col = colbase + ni * 8 + tg * 2;
            const float bb0 = bias[col], bb1 = bias[col + 1];
            const long long r0 = rowbase + mi * 16 + g;
            float2 v0 = make_float2(acc[mi][ni][0] + bb0, acc[mi][ni][1] + bb1);
            float2 v1 = make_float2(acc[mi][ni][2] + bb0, acc[mi][ni][3] + bb1);
            *(float2*)&C[r0 * N + col]       = v0;
            *(float2*)&C[(r0 + 8) * N + col] = v1;
        }
    }
}

// ---------------------------------------------------------------------------
extern "C" void kernel_launch(void* const* d_in, const int* in_sizes, int n_in,
                              void* d_out, int out_size) {
    const float* x    = (const float*)d_in[0];   // [T, K] fp32
    const float* w    = (const float*)d_in[1];   // [N, K] fp32
    const float* bias = (const float*)d_in[2];   // [N]    fp32
    // d_in[3] = hadamard matrix (unused; FWHT is computed in-warp)
    float* out = (float*)d_out;                  // [T, N] fp32

    __nv_bfloat16 *xq, *wq;
    cudaGetSymbolAddress((void**)&xq, g_xq);
    cudaGetSymbolAddress((void**)&wq, g_wq);

    rotate_quant_kernel<<<8192, 256>>>(x, w, xq, wq);

    dim3 grid(N_OUT / BN, T_TOK / BM);
    gemm_bf16_kernel<<<grid, 256>>>(xq, wq, bias, out, T_TOK, N_OUT, K_IN);
}

// round 3
// speedup vs baseline: 1.4163x; 1.4163x over previous
#include <cuda_runtime.h>
#include <cuda_bf16.h>
#include <cstdint>

// Problem shape (fixed by the dataset)
#define T_TOK 8192
#define K_IN  4096
#define N_OUT 4096
#define GROUP 32

// Dequantized scratch (bf16 is exact for MXFP4 values)
__device__ __nv_bfloat16 g_xq[(size_t)T_TOK * K_IN];   // 64 MB
__device__ __nv_bfloat16 g_wq[(size_t)N_OUT * K_IN];   // 32 MB

// ---------------------------------------------------------------------------
// Kernel 1: fused Hadamard rotate + MXFP4 quant-dequant, vectorized.
// Each lane holds 4 consecutive elements (float4). Group = 32 consecutive
// elements = 8 lanes x 4 regs. FWHT bits 0-1 in registers, bits 2-4 via
// shfl_xor (masks 1,2,4 stay within the 8-lane octet).
// ---------------------------------------------------------------------------
__global__ void rotate_quant_kernel(const float4* __restrict__ x4,
                                    const float4* __restrict__ w4,
                                    uint2* __restrict__ xq4,
                                    uint2* __restrict__ wq4) {
    const long long XW  = (long long)T_TOK * K_IN / 128;   // x warp-iters (128 elems each)
    const long long TOT = XW + (long long)N_OUT * K_IN / 128;

    const int lane = threadIdx.x & 31;
    long long warp  = (long long)blockIdx.x * (blockDim.x >> 5) + (threadIdx.x >> 5);
    long long nwarp = (long long)gridDim.x * (blockDim.x >> 5);

    for (long long it = warp; it < TOT; it += nwarp) {
        const float4* src; uint2* dst; long long blk;
        if (it < XW) { src = x4; dst = xq4; blk = it; }
        else         { src = w4; dst = wq4; blk = it - XW; }

        float4 v4 = src[blk * 32 + lane];
        float f0 = v4.x, f1 = v4.y, f2 = v4.z, f3 = v4.w;

        // FWHT bits 0,1 (within the 4 registers)
        {
            float s01 = f0 + f1, d01 = f0 - f1;
            float s23 = f2 + f3, d23 = f2 - f3;
            f0 = s01 + s23; f2 = s01 - s23;
            f1 = d01 + d23; f3 = d01 - d23;
        }
        // FWHT bits 2,3,4 (across 8 lanes of the octet)
        #pragma unroll
        for (int m = 1; m <= 4; m <<= 1) {
            float o0 = __shfl_xor_sync(0xffffffffu, f0, m);
            float o1 = __shfl_xor_sync(0xffffffffu, f1, m);
            float o2 = __shfl_xor_sync(0xffffffffu, f2, m);
            float o3 = __shfl_xor_sync(0xffffffffu, f3, m);
            if (lane & m) { f0 = o0 - f0; f1 = o1 - f1; f2 = o2 - f2; f3 = o3 - f3; }
            else          { f0 = f0 + o0; f1 = f1 + o1; f2 = f2 + o2; f3 = f3 + o3; }
        }
        const float c = 0.17677669529663688f;  // 1/sqrt(32)
        f0 *= c; f1 *= c; f2 *= c; f3 *= c;

        // group amax (4 regs, then 8-lane octet reduce)
        float amax = fmaxf(fmaxf(fabsf(f0), fabsf(f1)), fmaxf(fabsf(f2), fabsf(f3)));
        #pragma unroll
        for (int m = 1; m <= 4; m <<= 1)
            amax = fmaxf(amax, __shfl_xor_sync(0xffffffffu, amax, m));
        amax = fmaxf(amax, 1.1754943508222875e-38f);

        int e = (int)((__float_as_uint(amax) >> 23) & 0xFF) - 127 - 2;
        e = max(-127, min(127, e));
        const float scale  = ldexpf(1.0f, e);
        const float iscale = ldexpf(1.0f, -e);

        float f[4] = {f0, f1, f2, f3};
        uint32_t lo = 0, hi = 0;
        #pragma unroll
        for (int r = 0; r < 4; r++) {
            float s = f[r] * iscale;          // exact (power of 2)
            float a = fminf(fabsf(s), 6.0f);
            float q;
            if (a > 2.5f)       q = (a > 5.0f)  ? 6.0f : ((a > 3.5f)  ? 4.0f : 3.0f);
            else if (a > 1.25f) q = (a > 1.75f) ? 2.0f : 1.5f;
            else                q = (a > 0.75f) ? 1.0f : ((a > 0.25f) ? 0.5f : 0.0f);
            float res = copysignf(q, s) * scale;   // exact in bf16
            uint32_t b = (uint32_t)__bfloat16_as_ushort(__float2bfloat16(res));
            if (r < 2) lo |= b << (16 * r);
            else       hi |= b << (16 * (r - 2));
        }
        dst[blk * 32 + lane] = make_uint2(lo, hi);
    }
}

// ---------------------------------------------------------------------------
// Kernel 2: bf16 GEMM  C[M,N] = A[M,K] @ B[N,K]^T + bias, fp32 accumulate.
// 128x256 CTA tile, 512 threads (16 warps, 4x4), warp tile 32x64,
// mma.sync.m16n8k16 + ldmatrix.x4, 3-stage cp.async pipeline, BK=32.
// ---------------------------------------------------------------------------
#define BM 128
#define BN 256
#define BK 32
#define NSTG 3
#define LDE (BK + 8)                   // elements per smem row (16B pad)
#define A_ELE (BM * LDE)               // 5120 bf16
#define B_ELE (BN * LDE)               // 10240 bf16
#define STG_ELE (A_ELE + B_ELE)
#define SMEM_BYTES (NSTG * STG_ELE * 2)

__device__ __forceinline__ uint32_t smem_u32(const void* p) {
    uint32_t a;
    asm("{ .reg .u64 t; cvta.to.shared.u64 t, %1; cvt.u32.u64 %0, t; }"
        : "=r"(a) : "l"(p));
    return a;
}

__global__ __launch_bounds__(512, 1)
void gemm_bf16_kernel(const __nv_bfloat16* __restrict__ A,
                      const __nv_bfloat16* __restrict__ B,
                      const float* __restrict__ bias,
                      float* __restrict__ C) {
    extern __shared__ __nv_bfloat16 smem[];
    const uint32_t sbase = smem_u32(smem);

    const int tid = threadIdx.x;
    const int bm = blockIdx.y, bn = blockIdx.x;
    const int warp = tid >> 5, lane = tid & 31;
    const int wm = warp & 3;            // 0..3, 32 rows each
    const int wn = warp >> 2;           // 0..3, 64 cols each

    const __nv_bfloat16* Ab = A + (size_t)bm * BM * K_IN;
    const __nv_bfloat16* Bb = B + (size_t)bn * BN * K_IN;

    float acc[2][8][4];
    #pragma unroll
    for (int mi = 0; mi < 2; mi++)
        #pragma unroll
        for (int ni = 0; ni < 8; ni++)
            #pragma unroll
            for (int r = 0; r < 4; r++) acc[mi][ni][r] = 0.0f;

    // cp.async one K-chunk (BK=32 elems = 64B per row) into stage s
    auto load_stage = [&](int kt) {
        const int s = kt % NSTG;
        const uint32_t aS = sbase + s * STG_ELE * 2;
        const uint32_t bS = aS + A_ELE * 2;
        const int k0 = kt * BK;
        {   // A: 128 rows x 4 chunks = 512 tasks, 1/thread
            int row = tid >> 2, c = tid & 3;
            uint32_t dst = aS + (row * LDE + c * 8) * 2;
            const char* src = (const char*)(Ab + (size_t)row * K_IN + k0) + c * 16;
            asm volatile("cp.async.cg.shared.global [%0], [%1], 16;" :: "r"(dst), "l"(src));
        }
        #pragma unroll
        for (int j = 0; j < 2; j++) {   // B: 256 rows x 4 chunks = 1024 tasks
            int idx = tid + j * 512;
            int row = idx >> 2, c = idx & 3;
            uint32_t dst = bS + (row * LDE + c * 8) * 2;
            const char* src = (const char*)(Bb + (size_t)row * K_IN + k0) + c * 16;
            asm volatile("cp.async.cg.shared.global [%0], [%1], 16;" :: "r"(dst), "l"(src));
        }
        asm volatile("cp.async.commit_group;");
    };

    const int KT = K_IN / BK;           // 128
    load_stage(0);
    load_stage(1);

    for (int kt = 0; kt < KT; kt++) {
        asm volatile("cp.async.wait_group %0;" :: "n"(1));
        __syncthreads();

        if (kt + 2 < KT) load_stage(kt + 2);
        else asm volatile("cp.async.commit_group;");

        const int s = kt % NSTG;
        const uint32_t aS = sbase + s * STG_ELE * 2;
        const uint32_t bS = aS + A_ELE * 2;

        #pragma unroll
        for (int kk = 0; kk < BK; kk += 16) {
            // A fragments: 2 ldmatrix.x4 (rows wm*32+mi*16+lane%16, 16B chunk by lane/16)
            uint32_t a[2][4];
            #pragma unroll
            for (int mi = 0; mi < 2; mi++) {
                int row = wm * 32 + mi * 16 + (lane & 15);
                uint32_t addr = aS + (row * LDE + kk + ((lane >> 4) << 3)) * 2;
                asm volatile(
                    "ldmatrix.sync.aligned.m8n8.x4.shared.b16 {%0,%1,%2,%3}, [%4];"
                    : "=r"(a[mi][0]), "=r"(a[mi][1]), "=r"(a[mi][2]), "=r"(a[mi][3])
                    : "r"(addr));
            }
            // B fragments: 4 ldmatrix.x4, each serves two n8 tiles
            #pragma unroll
            for (int p = 0; p < 4; p++) {
                int row = wn * 64 + p * 16 + (lane & 15);
                uint32_t addr = bS + (row * LDE + kk + ((lane >> 4) << 3)) * 2;
                uint32_t b0, b1, b2, b3;
                asm volatile(
                    "ldmatrix.sync.aligned.m8n8.x4.shared.b16 {%0,%1,%2,%3}, [%4];"
                    : "=r"(b0), "=r"(b1), "=r"(b2), "=r"(b3) : "r"(addr));
                #pragma unroll
                for (int mi = 0; mi < 2; mi++) {
                    float* c0 = acc[mi][2 * p];
                    asm volatile(
                        "mma.sync.aligned.m16n8k16.row.col.f32.bf16.bf16.f32 "
                        "{%0,%1,%2,%3},{%4,%5,%6,%7},{%8,%9},{%0,%1,%2,%3};"
                        : "+f"(c0[0]), "+f"(c0[1]), "+f"(c0[2]), "+f"(c0[3])
                        : "r"(a[mi][0]), "r"(a[mi][1]), "r"(a[mi][2]), "r"(a[mi][3]),
                          "r"(b0), "r"(b2));
                    float* c1 = acc[mi][2 * p + 1];
                    asm volatile(
                        "mma.sync.aligned.m16n8k16.row.col.f32.bf16.bf16.f32 "
                        "{%0,%1,%2,%3},{%4,%5,%6,%7},{%8,%9},{%0,%1,%2,%3};"
                        : "+f"(c1[0]), "+f"(c1[1]), "+f"(c1[2]), "+f"(c1[3])
                        : "r"(a[mi][0]), "r"(a[mi][1]), "r"(a[mi][2]), "r"(a[mi][3]),
                          "r"(b1), "r"(b3));
                }
            }
        }
        __syncthreads();
    }

    // Epilogue: bias + fp32 stores (float2 per fragment row-pair)
    const size_t rowbase = (size_t)bm * BM + wm * 32 + (lane >> 2);
    const int colbase = bn * BN + wn * 64 + (lane & 3) * 2;
    #pragma unroll
    for (int ni = 0; ni < 8; ni++) {
        const int col = colbase + ni * 8;
        const float bb0 = __ldg(&bias[col]), bb1 = __ldg(&bias[col + 1]);
        #pragma unroll
        for (int mi = 0; mi < 2; mi++) {
            const size_t r0 = rowbase + mi * 16;
            float2 v0 = make_float2(acc[mi][ni][0] + bb0, acc[mi][ni][1] + bb1);
            float2 v1 = make_float2(acc[mi][ni][2] + bb0, acc[mi][ni][3] + bb1);
            *(float2*)&C[r0 * N_OUT + col]       = v0;
            *(float2*)&C[(r0 + 8) * N_OUT + col] = v1;
        }
    }
}

// ---------------------------------------------------------------------------
extern "C" void kernel_launch(void* const* d_in, const int* in_sizes, int n_in,
                              void* d_out, int out_size) {
    const float* x    = (const float*)d_in[0];   // [T, K] fp32
    const float* w    = (const float*)d_in[1];   // [N, K] fp32
    const float* bias = (const float*)d_in[2];   // [N]    fp32
    float* out = (float*)d_out;                  // [T, N] fp32

    __nv_bfloat16 *xq, *wq;
    cudaGetSymbolAddress((void**)&xq, g_xq);
    cudaGetSymbolAddress((void**)&wq, g_wq);

    rotate_quant_kernel<<<8192, 256>>>((const float4*)x, (const float4*)w,
                                       (uint2*)xq, (uint2*)wq);

    cudaFuncSetAttribute(gemm_bf16_kernel,
                         cudaFuncAttributeMaxDynamicSharedMemorySize, SMEM_BYTES);
    dim3 grid(N_OUT / BN, T_TOK / BM);
    gemm_bf16_kernel<<<grid, 512, SMEM_BYTES>>>(xq, wq, bias, out);
}

// round 4
// speedup vs baseline: 1.7015x; 1.2014x over previous
#include <cuda_runtime.h>
#include <cuda_bf16.h>
#include <cstdint>

// Problem shape (fixed by the dataset)
#define T_TOK 8192
#define K_IN  4096
#define N_OUT 4096
#define GROUP 32

// Dequantized scratch (bf16 is exact for MXFP4 values)
__device__ __nv_bfloat16 g_xq[(size_t)T_TOK * K_IN];   // 64 MB
__device__ __nv_bfloat16 g_wq[(size_t)N_OUT * K_IN];   // 32 MB

// ---------------------------------------------------------------------------
// Kernel 1: Hadamard rotate + MXFP4 qdq. One thread per 32-elem group,
// FWHT fully in registers (no shuffles), 8x LDG.128 in, 4x STG.128 out.
// ---------------------------------------------------------------------------
#define XGRP ((long long)T_TOK * K_IN / GROUP)   // 1048576
#define TGRP (XGRP + (long long)N_OUT * K_IN / GROUP)  // 1572864

__global__ __launch_bounds__(256)
void rotate_quant_kernel(const float4* __restrict__ x4,
                         const float4* __restrict__ w4,
                         uint4* __restrict__ xq4,
                         uint4* __restrict__ wq4) {
    long long g = (long long)blockIdx.x * blockDim.x + threadIdx.x;
    if (g >= TGRP) return;

    const float4* src;
    uint4* dst;
    if (g < XGRP) { src = x4 + g * 8;          dst = xq4 + g * 4; }
    else          { src = w4 + (g - XGRP) * 8; dst = wq4 + (g - XGRP) * 4; }

    float v[32];
    #pragma unroll
    for (int i = 0; i < 8; i++) {
        float4 t = src[i];
        v[4 * i] = t.x; v[4 * i + 1] = t.y; v[4 * i + 2] = t.z; v[4 * i + 3] = t.w;
    }

    // 5-stage FWHT in registers
    #pragma unroll
    for (int st = 1; st < 32; st <<= 1) {
        #pragma unroll
        for (int i = 0; i < 32; i++) {
            if (!(i & st)) {
                float a = v[i], b = v[i | st];
                v[i] = a + b; v[i | st] = a - b;
            }
        }
    }
    const float c = 0.17677669529663688f;   // 1/sqrt(32)
    float amax = 0.0f;
    #pragma unroll
    for (int i = 0; i < 32; i++) { v[i] *= c; amax = fmaxf(amax, fabsf(v[i])); }
    amax = fmaxf(amax, 1.1754943508222875e-38f);

    int e = (int)((__float_as_uint(amax) >> 23) & 0xFF) - 127 - 2;
    e = max(-127, min(127, e));
    const float scale  = ldexpf(1.0f, e);
    const float iscale = ldexpf(1.0f, -e);

    uint32_t wbuf[16];
    #pragma unroll
    for (int i = 0; i < 32; i += 2) {
        uint32_t pk = 0;
        #pragma unroll
        for (int r = 0; r < 2; r++) {
            float s = v[i + r] * iscale;      // exact (power of 2)
            float a = fminf(fabsf(s), 6.0f);
            float q;
            if (a > 2.5f)       q = (a > 5.0f)  ? 6.0f : ((a > 3.5f)  ? 4.0f : 3.0f);
            else if (a > 1.25f) q = (a > 1.75f) ? 2.0f : 1.5f;
            else                q = (a > 0.75f) ? 1.0f : ((a > 0.25f) ? 0.5f : 0.0f);
            float res = copysignf(q, s) * scale;   // exact in bf16
            pk |= (uint32_t)__bfloat16_as_ushort(__float2bfloat16(res)) << (16 * r);
        }
        wbuf[i >> 1] = pk;
    }
    #pragma unroll
    for (int i = 0; i < 4; i++)
        dst[i] = make_uint4(wbuf[4 * i], wbuf[4 * i + 1], wbuf[4 * i + 2], wbuf[4 * i + 3]);
}

// ---------------------------------------------------------------------------
// Kernel 2: bf16 GEMM  C[M,N] = A[M,K] @ B[N,K]^T + bias, fp32 accumulate.
// 128x256 CTA tile, 512 threads (16 warps, 4x4), warp tile 32x64.
// BK=64 (128B rows), 3-stage cp.async, ldmatrix.x4, A-frag double buffer.
// ---------------------------------------------------------------------------
#define BM 128
#define BN 256
#define BK 64
#define NSTG 3
#define LDE 72                          // bf16 per smem row (16B pad)
#define ROWB (LDE * 2)                  // 144 bytes
#define A_BYTES (BM * ROWB)             // 18432
#define B_BYTES (BN * ROWB)             // 36864
#define STG_B (A_BYTES + B_BYTES)       // 55296
#define MI_STEP (16 * ROWB)             // 2304 bytes per 16 rows
#define SMEM_BYTES (NSTG * STG_B + 1024)

__device__ __forceinline__ uint32_t smem_u32(const void* p) {
    uint32_t a;
    asm("{ .reg .u64 t; cvta.to.shared.u64 t, %1; cvt.u32.u64 %0, t; }"
        : "=r"(a) : "l"(p));
    return a;
}
#define LDSM4(r0, r1, r2, r3, addr)                                           \
    asm volatile("ldmatrix.sync.aligned.m8n8.x4.shared.b16 {%0,%1,%2,%3}, [%4];" \
                 : "=r"(r0), "=r"(r1), "=r"(r2), "=r"(r3) : "r"(addr))
#define MMA16816(c, a0, a1, a2, a3, b0, b1)                                   \
    asm volatile("mma.sync.aligned.m16n8k16.row.col.f32.bf16.bf16.f32 "       \
                 "{%0,%1,%2,%3},{%4,%5,%6,%7},{%8,%9},{%0,%1,%2,%3};"          \
                 : "+f"(c[0]), "+f"(c[1]), "+f"(c[2]), "+f"(c[3])              \
                 : "r"(a0), "r"(a1), "r"(a2), "r"(a3), "r"(b0), "r"(b1))

__global__ __launch_bounds__(512, 1)
void gemm_bf16_kernel(const __nv_bfloat16* __restrict__ A,
                      const __nv_bfloat16* __restrict__ B,
                      const float* __restrict__ bias,
                      float* __restrict__ C) {
    extern __shared__ char smem[];
    const uint32_t sbase = smem_u32(smem);
    float* sBias = (float*)(smem + NSTG * STG_B);

    const int tid = threadIdx.x;
    const int bm = blockIdx.y, bn = blockIdx.x;
    const int warp = tid >> 5, lane = tid & 31;
    const int wm = warp & 3, wn = warp >> 2;

    if (tid < 256) sBias[tid] = bias[bn * BN + tid];

    // --- cp.async task setup (6 x 16B per thread per stage) ---
    const __nv_bfloat16* Ab = A + (size_t)bm * BM * K_IN;
    const __nv_bfloat16* Bb = B + (size_t)bn * BN * K_IN;
    int arow0 = tid >> 3, ac0 = tid & 7;
    int arow1 = (tid + 512) >> 3, ac1 = ac0;
    uint32_t dA0 = arow0 * ROWB + ac0 * 16, dA1 = arow1 * ROWB + ac1 * 16;
    const char* sA0 = (const char*)(Ab + (size_t)arow0 * K_IN) + ac0 * 16;
    const char* sA1 = (const char*)(Ab + (size_t)arow1 * K_IN) + ac1 * 16;
    uint32_t dB[4]; const char* sB[4];
    #pragma unroll
    for (int j = 0; j < 4; j++) {
        int idx = tid + j * 512;
        int row = idx >> 3, cc = idx & 7;
        dB[j] = A_BYTES + row * ROWB + cc * 16;
        sB[j] = (const char*)(Bb + (size_t)row * K_IN) + cc * 16;
    }

    auto load_stage = [&](uint32_t off) {
        uint32_t base = sbase + off;
        asm volatile("cp.async.cg.shared.global [%0], [%1], 16;" :: "r"(base + dA0), "l"(sA0));
        asm volatile("cp.async.cg.shared.global [%0], [%1], 16;" :: "r"(base + dA1), "l"(sA1));
        #pragma unroll
        for (int j = 0; j < 4; j++)
            asm volatile("cp.async.cg.shared.global [%0], [%1], 16;" :: "r"(base + dB[j]), "l"(sB[j]));
        asm volatile("cp.async.commit_group;");
        sA0 += BK * 2; sA1 += BK * 2;
        #pragma unroll
        for (int j = 0; j < 4; j++) sB[j] += BK * 2;
    };

    // --- fragment base addresses (hoisted) ---
    const uint32_t aBase0 = sbase + (wm * 32 + (lane & 15)) * ROWB + ((lane >> 4) << 4);
    const uint32_t bBase0 = sbase + A_BYTES + (wn * 64 + (lane & 15)) * ROWB + ((lane >> 4) << 4);

    float acc[2][8][4];
    #pragma unroll
    for (int mi = 0; mi < 2; mi++)
        #pragma unroll
        for (int ni = 0; ni < 8; ni++)
            #pragma unroll
            for (int r = 0; r < 4; r++) acc[mi][ni][r] = 0.0f;

    const int KT = K_IN / BK;  // 64
    load_stage(0);
    load_stage(STG_B);
    uint32_t ldOff = 2 * STG_B;   // stage being filled next
    uint32_t cOff  = 0;           // stage being consumed

    for (int kt = 0; kt < KT; kt++) {
        asm volatile("cp.async.wait_group %0;" :: "n"(1));
        __syncthreads();

        if (kt + 2 < KT) {
            load_stage(ldOff);
            ldOff += STG_B; if (ldOff == NSTG * STG_B) ldOff = 0;
        } else {
            asm volatile("cp.async.commit_group;");
        }

        const uint32_t aOff = aBase0 + cOff;
        const uint32_t bOff = bBase0 + cOff;

        uint32_t aF[2][2][4];
        LDSM4(aF[0][0][0], aF[0][0][1], aF[0][0][2], aF[0][0][3], aOff);
        LDSM4(aF[0][1][0], aF[0][1][1], aF[0][1][2], aF[0][1][3], aOff + MI_STEP);

        #pragma unroll
        for (int ks = 0; ks < 4; ks++) {
            const int cur = ks & 1;
            if (ks < 3) {
                const int nxt = cur ^ 1;
                LDSM4(aF[nxt][0][0], aF[nxt][0][1], aF[nxt][0][2], aF[nxt][0][3],
                      aOff + (ks + 1) * 32);
                LDSM4(aF[nxt][1][0], aF[nxt][1][1], aF[nxt][1][2], aF[nxt][1][3],
                      aOff + MI_STEP + (ks + 1) * 32);
            }
            #pragma unroll
            for (int p = 0; p < 4; p++) {
                uint32_t b0, b1, b2, b3;
                LDSM4(b0, b1, b2, b3, bOff + p * MI_STEP + ks * 32);
                #pragma unroll
                for (int mi = 0; mi < 2; mi++) {
                    MMA16816(acc[mi][2 * p],     aF[cur][mi][0], aF[cur][mi][1],
                             aF[cur][mi][2], aF[cur][mi][3], b0, b2);
                    MMA16816(acc[mi][2 * p + 1], aF[cur][mi][0], aF[cur][mi][1],
                             aF[cur][mi][2], aF[cur][mi][3], b1, b3);
                }
            }
        }
        cOff += STG_B; if (cOff == NSTG * STG_B) cOff = 0;
    }

    // Epilogue: bias (from smem) + fp32 stores
    const size_t rowbase = (size_t)bm * BM + wm * 32 + (lane >> 2);
    const int coll = wn * 64 + (lane & 3) * 2;
    const int colbase = bn * BN + coll;
    #pragma unroll
    for (int ni = 0; ni < 8; ni++) {
        const float bb0 = sBias[coll + ni * 8];
        const float bb1 = sBias[coll + ni * 8 + 1];
        #pragma unroll
        for (int mi = 0; mi < 2; mi++) {
            const size_t r0 = rowbase + mi * 16;
            float2 v0 = make_float2(acc[mi][ni][0] + bb0, acc[mi][ni][1] + bb1);
            float2 v1 = make_float2(acc[mi][ni][2] + bb0, acc[mi][ni][3] + bb1);
            *(float2*)&C[r0 * N_OUT + colbase + ni * 8]       = v0;
            *(float2*)&C[(r0 + 8) * N_OUT + colbase + ni * 8] = v1;
        }
    }
}

// ---------------------------------------------------------------------------
extern "C" void kernel_launch(void* const* d_in, const int* in_sizes, int n_in,
                              void* d_out, int out_size) {
    const float* x    = (const float*)d_in[0];   // [T, K] fp32
    const float* w    = (const float*)d_in[1];   // [N, K] fp32
    const float* bias = (const float*)d_in[2];   // [N]    fp32
    float* out = (float*)d_out;                  // [T, N] fp32

    __nv_bfloat16 *xq, *wq;
    cudaGetSymbolAddress((void**)&xq, g_xq);
    cudaGetSymbolAddress((void**)&wq, g_wq);

    rotate_quant_kernel<<<(int)(TGRP / 256), 256>>>(
        (const float4*)x, (const float4*)w, (uint4*)xq, (uint4*)wq);

    cudaFuncSetAttribute(gemm_bf16_kernel,
                         cudaFuncAttributeMaxDynamicSharedMemorySize, SMEM_BYTES);
    dim3 grid(N_OUT / BN, T_TOK / BM);
    gemm_bf16_kernel<<<grid, 512, SMEM_BYTES>>>(xq, wq, bias, out);
}